// round 1
// baseline (speedup 1.0000x reference)
#include <cuda_runtime.h>
#include <cuda_bf16.h>

// MarginRankingLoss: x[V=4096, C=128, T=128] fp32, target[V,C] int64 -> scalar.
// loss = ( sum_{v,c,t} max(0, x - x[target] + 0.5) - 0.5*V*C ) / (V*C*(T-1))
// (the target position always contributes exactly 0.5, subtracted analytically)

#define NROWS (4096 * 128)   // V*C
#define TDIM 128
#define NBLOCKS 2048
#define NTHREADS 256

__device__ double g_mrl_sum;

__global__ void mrl_zero_kernel() {
    g_mrl_sum = 0.0;
}

__global__ __launch_bounds__(NTHREADS) void mrl_main_kernel(
    const float4* __restrict__ x,          // [NROWS * 32] float4 view
    const long long* __restrict__ target)  // [NROWS]
{
    const int lane  = threadIdx.x & 31;
    const int warp  = (blockIdx.x * NTHREADS + threadIdx.x) >> 5;
    const int nwarp = (NBLOCKS * NTHREADS) >> 5;

    float acc = 0.0f;

    for (int row = warp; row < NROWS; row += nwarp) {
        const float4 v = x[row * 32 + lane];
        const int t = (int)target[row];

        // extract x[row][t]: lane t>>2 holds it in element t&3
        float p = (t & 2) ? ((t & 1) ? v.w : v.z)
                          : ((t & 1) ? v.y : v.x);
        const float pos = __shfl_sync(0xffffffffu, p, t >> 2);

        const float b = 0.5f - pos;
        acc += fmaxf(v.x + b, 0.0f) + fmaxf(v.y + b, 0.0f)
             + fmaxf(v.z + b, 0.0f) + fmaxf(v.w + b, 0.0f);
    }

    // warp reduce
    #pragma unroll
    for (int o = 16; o; o >>= 1)
        acc += __shfl_xor_sync(0xffffffffu, acc, o);

    __shared__ float smem[NTHREADS / 32];
    if (lane == 0) smem[threadIdx.x >> 5] = acc;
    __syncthreads();

    if (threadIdx.x == 0) {
        float bsum = 0.0f;
        #pragma unroll
        for (int w = 0; w < NTHREADS / 32; w++) bsum += smem[w];
        atomicAdd(&g_mrl_sum, (double)bsum);
    }
}

__global__ void mrl_finalize_kernel(float* __restrict__ out) {
    // subtract the target-position hinge (exactly 0.5 per row), then mean
    const double corrected = g_mrl_sum - 0.5 * (double)NROWS;
    out[0] = (float)(corrected / ((double)NROWS * (double)(TDIM - 1)));
}

extern "C" void kernel_launch(void* const* d_in, const int* in_sizes, int n_in,
                              void* d_out, int out_size) {
    const float4*    x   = (const float4*)d_in[0];
    const long long* tgt = (const long long*)d_in[1];
    float*           out = (float*)d_out;

    mrl_zero_kernel<<<1, 1>>>();
    mrl_main_kernel<<<NBLOCKS, NTHREADS>>>(x, tgt);
    mrl_finalize_kernel<<<1, 1>>>(out);
}